// round 9
// baseline (speedup 1.0000x reference)
#include <cuda_runtime.h>
#include <cstddef>

// Problem constants (fixed by the dataset)
#define TBL 32      // T
#define DIM 64      // D
#define GRP 1024    // bags per table value = num_bags / TBL

// One warp per bag, float4 layout: 16 lanes cover one 256B row; the two
// half-warps fetch DIFFERENT rows in the same LDG.128 instruction.
// 4 LDG.128 per iteration = 8 rows in flight per warp, tuned to fit 32 regs
// so occupancy reaches 8 blocks (64 warps/SM): 64w x 8 rows = 512 rows in
// flight per SM.
// Bags are table-grouped so bags sharing table slice W[:, t, :] run
// temporally adjacent and repeated indices become L2 hits.
// End: halves combined with 4x shfl.xor(16), half-warp streaming store.
__global__ void __launch_bounds__(256, 8)
embbag_kernel(const float* __restrict__ W,
              const int*   __restrict__ feat,
              const int*   __restrict__ off,
              float*       __restrict__ out,
              int num_bags)
{
    int gwarp = (blockIdx.x * blockDim.x + threadIdx.x) >> 5;
    int lane  = threadIdx.x & 31;
    if (gwarp >= num_bags) return;

    // Table-grouped schedule: warps [t*GRP, (t+1)*GRP) handle table t.
    const int table = gwarp >> 10;           // g / 1024
    const int group = gwarp & (GRP - 1);     // g % 1024
    const int bag   = (group << 5) + table;  // original bag id; bag % 32 == table

    const int start = off[bag];
    const int end   = off[bag + 1];

    const int half = lane >> 4;              // which row of the pair
    const int hl   = lane & 15;              // float4 slot within the row

    // Row e lives at float4 index (e*TBL + table)*16 + hl.
    const float4* Wq = (const float4*)W + (size_t)table * (DIM / 4) + hl;

    float4 acc = make_float4(0.f, 0.f, 0.f, 0.f);

    int j = start;
    // Main loop: 8 rows per iteration (4 LDG.128, each covering 2 rows).
    for (; j + 8 <= end; j += 8) {
        int e0 = __ldcs(feat + j + 0 + half);
        int e1 = __ldcs(feat + j + 2 + half);
        int e2 = __ldcs(feat + j + 4 + half);
        int e3 = __ldcs(feat + j + 6 + half);
        float4 v0 = __ldg(Wq + (size_t)e0 * (TBL * DIM / 4));
        float4 v1 = __ldg(Wq + (size_t)e1 * (TBL * DIM / 4));
        float4 v2 = __ldg(Wq + (size_t)e2 * (TBL * DIM / 4));
        float4 v3 = __ldg(Wq + (size_t)e3 * (TBL * DIM / 4));
        acc.x += (v0.x + v1.x) + (v2.x + v3.x);
        acc.y += (v0.y + v1.y) + (v2.y + v3.y);
        acc.z += (v0.z + v1.z) + (v2.z + v3.z);
        acc.w += (v0.w + v1.w) + (v2.w + v3.w);
    }
    // Pair tail
    for (; j + 2 <= end; j += 2) {
        int e = __ldcs(feat + j + half);
        float4 v = __ldg(Wq + (size_t)e * (TBL * DIM / 4));
        acc.x += v.x; acc.y += v.y; acc.z += v.z; acc.w += v.w;
    }
    // Single-row tail (only half 0 contributes)
    if (j < end) {
        int e = __ldcs(feat + j);
        if (half == 0) {
            float4 v = __ldg(Wq + (size_t)e * (TBL * DIM / 4));
            acc.x += v.x; acc.y += v.y; acc.z += v.z; acc.w += v.w;
        }
    }

    // Combine the two half-warp partial sums (same dims, different rows).
    acc.x += __shfl_xor_sync(0xFFFFFFFFu, acc.x, 16);
    acc.y += __shfl_xor_sync(0xFFFFFFFFu, acc.y, 16);
    acc.z += __shfl_xor_sync(0xFFFFFFFFu, acc.z, 16);
    acc.w += __shfl_xor_sync(0xFFFFFFFFu, acc.w, 16);

    // Half-warp streaming store: 16 lanes x float4 = 256B row, coalesced.
    if (half == 0) {
        float4* o = (float4*)(out + (size_t)bag * DIM) + hl;
        __stcs(o, acc);
    }
}

extern "C" void kernel_launch(void* const* d_in, const int* in_sizes, int n_in,
                              void* d_out, int out_size)
{
    const float* W    = (const float*)d_in[0];   // (E, T, D) fp32
    const int*   feat = (const int*)d_in[1];     // (B*T*L,) int32
    const int*   off  = (const int*)d_in[2];     // (B*T+1,) int32

    int num_bags = in_sizes[2] - 1;              // B*T = 32768
    float* out = (float*)d_out;                  // (B, T, D) fp32

    int threads = 256;                           // 8 warps = 8 bags per block
    int total_threads = num_bags * 32;
    int blocks = (total_threads + threads - 1) / threads;

    embbag_kernel<<<blocks, threads>>>(W, feat, off, out, num_bags);
}